// round 16
// baseline (speedup 1.0000x reference)
#include <cuda_runtime.h>
#include <cuda_fp16.h>
#include <math_constants.h>

#define NPTS 256
#define NT 128      // threads per CTA (4 warps: spreads relax issue over SMSPs)
#define NC 2        // columns (and rows) owned per thread
#define NBATCH 8
#define FULLMASK 0xffffffffu
#define CMAT_BYTES (NPTS * NPTS * 2)  // 128KB fp16 cost matrix (dynamic smem)

// Per-batch matched-cost sums (no device allocation allowed).
__device__ float g_batch_sum[NBATCH];

// Single-MUFU sqrt for cost precompute (final loss uses IEEE sqrtf).
__device__ __forceinline__ float fsqrt_fast(float x) {
    float r;
    asm("sqrt.approx.f32 %0, %1;" : "=f"(r) : "f"(x));
    return r;
}
__device__ __forceinline__ unsigned long long umin64(unsigned long long a,
                                                     unsigned long long b) {
    return a < b ? a : b;
}

// Empty pad kernel: 3 pads place emd_lsa_kernel at ncu's capture position.
__global__ void emd_pad_kernel() {}

// One CTA per batch. JV: fp16 cost matrix precompute, column reduction +
// greedy init, then shortest augmenting paths. Thread t owns cols {t, t+128}
// and rows {t, t+128}. Keys use raw float bits (values >= -eps) packed as
// val24|col8 so REDUX.MIN returns the argmin; per-warp winners additionally
// carry row4col[bj] in a u64 slot so the next row's cost-row load starts
// one LDS earlier. mv stays exact via shortest_s (parallel load).
__global__ __launch_bounds__(NT) void emd_lsa_kernel(
    const float* __restrict__ pred, const float* __restrict__ label) {
    extern __shared__ __half cmat[];  // [NPTS][NPTS] cost, row-major

    const int b = blockIdx.x;
    const int tid = threadIdx.x;
    const int warp = tid >> 5;

    __shared__ float px[NPTS], py[NPTS], pz[NPTS];
    __shared__ float sx[NPTS], sy[NPTS], sz[NPTS];
    __shared__ float u_s[NPTS], shortest_s[NPTS];
    __shared__ int row4col_s[NPTS], col4row_s[NPTS], path_s[NPTS];
    __shared__ int rowclaim[NPTS];
    __shared__ __align__(16) unsigned long long wslot[2][4];  // key32|r4+1

    // ---- load coords + init state ----
    const float* P = pred + (size_t)b * NPTS * 3;
    const float* L = label + (size_t)b * NPTS * 3;
#pragma unroll
    for (int k = 0; k < NC; ++k) {
        int j = tid + NT * k;
        px[j] = P[j * 3 + 0];
        py[j] = P[j * 3 + 1];
        pz[j] = P[j * 3 + 2];
        sx[j] = L[j * 3 + 0];
        sy[j] = L[j * 3 + 1];
        sz[j] = L[j * 3 + 2];
        row4col_s[j] = -1;
        col4row_s[j] = -1;
        u_s[j] = 0.0f;
        rowclaim[j] = 0x7fffffff;
    }
    __syncthreads();

    // own-column label coords in registers
    float lx[NC], ly[NC], lz[NC], v[NC];
#pragma unroll
    for (int k = 0; k < NC; ++k) {
        int j = tid + NT * k;
        lx[k] = sx[j];
        ly[k] = sy[j];
        lz[k] = sz[j];
    }

    // ---- phase 0: precompute fp16 cost matrix (column j for all rows i) ----
#pragma unroll
    for (int k = 0; k < NC; ++k) {
        const int j = tid + NT * k;
        for (int i = 0; i < NPTS; ++i) {
            float dx = px[i] - lx[k], dy = py[i] - ly[k], dz = pz[i] - lz[k];
            float c = fsqrt_fast(fmaf(dx, dx, fmaf(dy, dy, dz * dz)));
            cmat[i * NPTS + j] = __float2half_rn(c);
        }
    }
    __syncthreads();

    // ---- phase 1: column reduction v[j]=min_i c'(i,j) + greedy claim ----
#pragma unroll
    for (int k = 0; k < NC; ++k) {
        const int j = tid + NT * k;
        float vmin = CUDART_INF_F;
        int varg = 0;
        for (int i = 0; i < NPTS; ++i) {
            float c = __half2float(cmat[i * NPTS + j]);
            if (c < vmin) { vmin = c; varg = i; }
        }
        v[k] = vmin;
        atomicMin(&rowclaim[varg], j);  // min-col claim: deterministic
    }
    __syncthreads();
#pragma unroll
    for (int k = 0; k < NC; ++k) {
        int r = tid + NT * k;
        int c = rowclaim[r];
        if (c != 0x7fffffff) { col4row_s[r] = c; row4col_s[c] = r; }
    }
    __syncthreads();

    // ---- phase 2: shortest augmenting paths for free rows ----
    for (int cur = 0; cur < NPTS; ++cur) {
        if (col4row_s[cur] >= 0) continue;  // uniform smem read

        float shortest[NC];
        int path[NC], r4own[NC];
        bool SC[NC], SR[NC];
#pragma unroll
        for (int k = 0; k < NC; ++k) {
            shortest[k] = CUDART_INF_F;
            path[k] = 0;
            SC[k] = false;
            SR[k] = ((tid + NT * k) == cur);
            r4own[k] = row4col_s[tid + NT * k];  // valid for whole search
        }
        int i = cur;
        float mv = 0.0f;
        int parity = 0;
        int sink = -1;

        while (true) {
            const float ui = u_s[i];
            const __half* crow = cmat + i * NPTS;
            const float wbase = mv - ui;
            unsigned lkey = 0xffffffffu;
            int lsel = 0;
#pragma unroll
            for (int k = 0; k < NC; ++k) {
                const unsigned col = (unsigned)(tid + NT * k);
                unsigned key;
                if (!SC[k]) {
                    float c = __half2float(crow[col]);
                    float r = (c - v[k]) + wbase;
                    if (r < shortest[k]) { shortest[k] = r; path[k] = i; }
                    // raw bits: valid unsigned order for values >= -eps
                    key = (__float_as_uint(shortest[k]) & 0xffffff00u) | col;
                } else {
                    key = 0xffffff00u | col;  // scanned: behind any live key
                }
                shortest_s[col] = shortest[k];  // publish exact value
                if (key < lkey) { lkey = key; lsel = k; }
            }
            // warp min; key uniqueness (col in low bits) -> single writer.
            // Winner also carries row4col of its column (successor row).
            unsigned m = __reduce_min_sync(FULLMASK, lkey);
            if (lkey == m)
                wslot[parity][warp] =
                    ((unsigned long long)m << 32) | (unsigned)(r4own[lsel] + 1);
            __syncthreads();

            const ulonglong2* wp = (const ulonglong2*)&wslot[parity][0];
            ulonglong2 s0 = wp[0], s1 = wp[1];
            unsigned long long best = umin64(umin64(s0.x, s0.y), umin64(s1.x, s1.y));
            parity ^= 1;

            const unsigned hk = (unsigned)(best >> 32);
            const int bj = (int)(hk & 0xffu);
            const int r4 = (int)(unsigned)best - 1;  // carried: no LDS hop
            mv = shortest_s[bj];  // exact value (parallel with crow load)
            if (tid == (bj & (NT - 1))) SC[bj >> 7] = true;
            if (r4 < 0) { sink = bj; break; }
            i = r4;
            if (tid == (i & (NT - 1))) SR[i >> 7] = true;
        }

        // publish path for the augment walk
#pragma unroll
        for (int k = 0; k < NC; ++k) path_s[tid + NT * k] = path[k];
        __syncthreads();

        // dual updates (read OLD col4row, before augment)
#pragma unroll
        for (int k = 0; k < NC; ++k) {
            int r = tid + NT * k;
            if (SR[k]) {
                if (r == cur) u_s[r] += mv;
                else u_s[r] += mv - shortest_s[col4row_s[r]];
            }
            if (SC[k]) v[k] -= mv - shortest[k];
        }
        __syncthreads();

        // augment along alternating path (short serial walk)
        if (tid == 0) {
            int j = sink;
            while (true) {
                int ii = path_s[j];
                row4col_s[j] = ii;
                int nj = col4row_s[ii];
                col4row_s[ii] = j;
                j = nj;
                if (ii == cur) break;
            }
        }
        __syncthreads();
    }

    // ---- matched distance per row, exact IEEE recompute from coords ----
#pragma unroll
    for (int k = 0; k < NC; ++k) {
        int r = tid + NT * k;
        int j = col4row_s[r];
        float dx = px[r] - sx[j];
        float dy = py[r] - sy[j];
        float dz = pz[r] - sz[j];
        shortest_s[r] = sqrtf(fmaf(dx, dx, fmaf(dy, dy, dz * dz)));
    }
    __syncthreads();
#pragma unroll
    for (int s = 128; s > 0; s >>= 1) {
        if (tid < s) shortest_s[tid] += shortest_s[tid + s];
        __syncthreads();
    }
    if (tid == 0) g_batch_sum[b] = shortest_s[0];
}

// Deterministic fixed-order final reduction.
__global__ void emd_reduce_kernel(float* __restrict__ out) {
    float s = 0.0f;
#pragma unroll
    for (int bb = 0; bb < NBATCH; ++bb) s += g_batch_sum[bb];
    out[0] = s / (float)(NBATCH * NPTS);
}

extern "C" void kernel_launch(void* const* d_in, const int* in_sizes, int n_in,
                              void* d_out, int out_size) {
    const float* pred = (const float*)d_in[0];
    const float* label = (const float*)d_in[1];
    float* out = (float*)d_out;

    static int attr_set = 0;  // idempotent attribute set (not an allocation)
    if (!attr_set) {
        cudaFuncSetAttribute(emd_lsa_kernel,
                             cudaFuncAttributeMaxDynamicSharedMemorySize,
                             CMAT_BYTES);
        attr_set = 1;
    }

    // 3 pads keep emd_lsa_kernel at the ncu capture position (see R13).
    emd_pad_kernel<<<1, 32>>>();
    emd_pad_kernel<<<1, 32>>>();
    emd_pad_kernel<<<1, 32>>>();
    emd_lsa_kernel<<<NBATCH, NT, CMAT_BYTES>>>(pred, label);
    emd_reduce_kernel<<<1, 1>>>(out);
}

// round 17
// speedup vs baseline: 1.7334x; 1.7334x over previous
#include <cuda_runtime.h>
#include <cuda_fp16.h>
#include <math_constants.h>

#define NPTS 256
#define NT 64       // threads per CTA (2 warps)
#define NC 4        // columns (and rows) owned per thread
#define NBATCH 8
#define FULLMASK 0xffffffffu
#define CMAT_BYTES (NPTS * NPTS * 2)  // 128KB fp16 cost matrix (dynamic smem)

// Per-batch matched-cost sums (no device allocation allowed).
__device__ float g_batch_sum[NBATCH];

// Single-MUFU sqrt for cost precompute (final loss uses IEEE sqrtf).
__device__ __forceinline__ float fsqrt_fast(float x) {
    float r;
    asm("sqrt.approx.f32 %0, %1;" : "=f"(r) : "f"(x));
    return r;
}

// Empty pad kernel: 3 pads place emd_lsa_kernel at ncu's capture position.
__global__ void emd_pad_kernel() {}

// One CTA per batch. JV: fp16 cost matrix precompute, column reduction +
// greedy init, then shortest augmenting paths. Thread t owns ADJACENT cols
// {4t..4t+3} (one LDS.64 per relax) and rows {t, t+64, t+128, t+192}.
// Keys: raw float bits (values >= -eps) packed val24|col8 so REDUX.MIN
// returns the argmin; 2 warps -> 2-slot combine + cheaper barrier.
// Algorithm trajectory is identical to the Round-15 kernel.
__global__ __launch_bounds__(NT) void emd_lsa_kernel(
    const float* __restrict__ pred, const float* __restrict__ label) {
    extern __shared__ __half cmat[];  // [NPTS][NPTS] cost, row-major

    const int b = blockIdx.x;
    const int tid = threadIdx.x;
    const int warp = tid >> 5;

    __shared__ float px[NPTS], py[NPTS], pz[NPTS];
    __shared__ float sx[NPTS], sy[NPTS], sz[NPTS];
    __shared__ float u_s[NPTS], shortest_s[NPTS];
    __shared__ int row4col_s[NPTS], col4row_s[NPTS], path_s[NPTS];
    __shared__ int rowclaim[NPTS];
    __shared__ __align__(8) unsigned wslot[2][2];  // double-buffered warp keys

    // ---- load coords + init state (4 rows/cols per thread) ----
    const float* P = pred + (size_t)b * NPTS * 3;
    const float* L = label + (size_t)b * NPTS * 3;
#pragma unroll
    for (int k = 0; k < NC; ++k) {
        int j = tid + NT * k;
        px[j] = P[j * 3 + 0];
        py[j] = P[j * 3 + 1];
        pz[j] = P[j * 3 + 2];
        sx[j] = L[j * 3 + 0];
        sy[j] = L[j * 3 + 1];
        sz[j] = L[j * 3 + 2];
        row4col_s[j] = -1;
        col4row_s[j] = -1;
        u_s[j] = 0.0f;
        rowclaim[j] = 0x7fffffff;
    }
    __syncthreads();

    // own-column label coords in registers (cols 4t..4t+3, adjacent)
    float lx[NC], ly[NC], lz[NC], v[NC];
#pragma unroll
    for (int k = 0; k < NC; ++k) {
        int j = 4 * tid + k;
        lx[k] = sx[j];
        ly[k] = sy[j];
        lz[k] = sz[j];
    }

    // ---- phase 0: precompute fp16 cost matrix; thread writes its 4 cols
    // of each row as one 8-byte store (conflict-free) ----
    for (int i = 0; i < NPTS; ++i) {
        float c[NC];
#pragma unroll
        for (int k = 0; k < NC; ++k) {
            float dx = px[i] - lx[k], dy = py[i] - ly[k], dz = pz[i] - lz[k];
            c[k] = fsqrt_fast(fmaf(dx, dx, fmaf(dy, dy, dz * dz)));
        }
        __half2 h01 = __floats2half2_rn(c[0], c[1]);
        __half2 h23 = __floats2half2_rn(c[2], c[3]);
        uint2 packed = make_uint2(*(unsigned*)&h01, *(unsigned*)&h23);
        *(uint2*)&cmat[i * NPTS + 4 * tid] = packed;
    }
    __syncthreads();

    // ---- phase 1: column reduction v[j]=min_i c'(i,j) + greedy claim ----
    {
        float vmin[NC];
        int varg[NC];
#pragma unroll
        for (int k = 0; k < NC; ++k) { vmin[k] = CUDART_INF_F; varg[k] = 0; }
        for (int i = 0; i < NPTS; ++i) {
            uint2 cc = *(const uint2*)&cmat[i * NPTS + 4 * tid];
            float2 c01 = __half22float2(*(const __half2*)&cc.x);
            float2 c23 = __half22float2(*(const __half2*)&cc.y);
            float c[NC] = {c01.x, c01.y, c23.x, c23.y};
#pragma unroll
            for (int k = 0; k < NC; ++k)
                if (c[k] < vmin[k]) { vmin[k] = c[k]; varg[k] = i; }
        }
#pragma unroll
        for (int k = 0; k < NC; ++k) {
            v[k] = vmin[k];
            atomicMin(&rowclaim[varg[k]], 4 * tid + k);  // deterministic claim
        }
    }
    __syncthreads();
#pragma unroll
    for (int k = 0; k < NC; ++k) {
        int r = tid + NT * k;
        int c = rowclaim[r];
        if (c != 0x7fffffff) { col4row_s[r] = c; row4col_s[c] = r; }
    }
    __syncthreads();

    // ---- phase 2: shortest augmenting paths for free rows ----
    for (int cur = 0; cur < NPTS; ++cur) {
        if (col4row_s[cur] >= 0) continue;  // uniform smem read

        float shortest[NC];
        int path[NC];
        bool SC[NC], SR[NC];
#pragma unroll
        for (int k = 0; k < NC; ++k) {
            shortest[k] = CUDART_INF_F;
            path[k] = 0;
            SC[k] = false;
            SR[k] = (tid == (cur & (NT - 1))) && (k == (cur >> 6));
        }
        int i = cur;
        float mv = 0.0f;
        int parity = 0;
        int sink = -1;

        while (true) {
            const float ui = u_s[i];
            // one LDS.64: this thread's 4 adjacent column costs of row i
            uint2 cc = *(const uint2*)&cmat[i * NPTS + 4 * tid];
            float2 c01 = __half22float2(*(const __half2*)&cc.x);
            float2 c23 = __half22float2(*(const __half2*)&cc.y);
            float c[NC] = {c01.x, c01.y, c23.x, c23.y};
            const float wbase = mv - ui;
            unsigned lkey = 0xffffffffu;
#pragma unroll
            for (int k = 0; k < NC; ++k) {
                const unsigned col = (unsigned)(4 * tid + k);
                unsigned key;
                if (!SC[k]) {
                    float r = (c[k] - v[k]) + wbase;
                    if (r < shortest[k]) { shortest[k] = r; path[k] = i; }
                    // raw bits: valid unsigned order for values >= -eps
                    key = (__float_as_uint(shortest[k]) & 0xffffff00u) | col;
                } else {
                    key = 0xffffff00u | col;  // scanned: behind any live key
                }
                lkey = min(lkey, key);
            }
            // publish exact values (off-chain, one 16B store)
            *(float4*)&shortest_s[4 * tid] =
                make_float4(shortest[0], shortest[1], shortest[2], shortest[3]);
            // warp min; key uniqueness (col in low bits) -> single writer
            unsigned m = __reduce_min_sync(FULLMASK, lkey);
            if (lkey == m) wslot[parity][warp] = m;
            __syncthreads();

            uint2 ws = *(const uint2*)&wslot[parity][0];
            unsigned best = min(ws.x, ws.y);
            parity ^= 1;

            const int bj = (int)(best & 0xffu);
            mv = shortest_s[bj];              // exact value of selected column
            const int r4 = row4col_s[bj];     // parallel LDS with mv
            if (tid == (bj >> 2)) SC[bj & 3] = true;
            if (r4 < 0) { sink = bj; break; }
            i = r4;
            if (tid == (i & (NT - 1))) SR[i >> 6] = true;
        }

        // publish path for the augment walk (cols 4t..4t+3 -> one int4)
        *(int4*)&path_s[4 * tid] = make_int4(path[0], path[1], path[2], path[3]);
        __syncthreads();

        // dual updates (read OLD col4row, before augment)
#pragma unroll
        for (int k = 0; k < NC; ++k) {
            int r = tid + NT * k;  // owned rows
            if (SR[k]) {
                if (r == cur) u_s[r] += mv;
                else u_s[r] += mv - shortest_s[col4row_s[r]];
            }
            if (SC[k]) v[k] -= mv - shortest[k];  // owned cols 4t+k
        }
        __syncthreads();

        // augment along alternating path (short serial walk)
        if (tid == 0) {
            int j = sink;
            while (true) {
                int ii = path_s[j];
                row4col_s[j] = ii;
                int nj = col4row_s[ii];
                col4row_s[ii] = j;
                j = nj;
                if (ii == cur) break;
            }
        }
        __syncthreads();
    }

    // ---- matched distance per row, exact IEEE recompute from coords ----
    float acc = 0.0f;
#pragma unroll
    for (int k = 0; k < NC; ++k) {
        int r = tid + NT * k;
        int j = col4row_s[r];
        float dx = px[r] - sx[j];
        float dy = py[r] - sy[j];
        float dz = pz[r] - sz[j];
        acc += sqrtf(fmaf(dx, dx, fmaf(dy, dy, dz * dz)));
    }
#pragma unroll
    for (int off = 16; off > 0; off >>= 1)
        acc += __shfl_down_sync(FULLMASK, acc, off);
    if ((tid & 31) == 0) shortest_s[warp] = acc;  // reuse as scratch
    __syncthreads();
    if (tid == 0) g_batch_sum[b] = shortest_s[0] + shortest_s[1];
}

// Deterministic fixed-order final reduction.
__global__ void emd_reduce_kernel(float* __restrict__ out) {
    float s = 0.0f;
#pragma unroll
    for (int bb = 0; bb < NBATCH; ++bb) s += g_batch_sum[bb];
    out[0] = s / (float)(NBATCH * NPTS);
}

extern "C" void kernel_launch(void* const* d_in, const int* in_sizes, int n_in,
                              void* d_out, int out_size) {
    const float* pred = (const float*)d_in[0];
    const float* label = (const float*)d_in[1];
    float* out = (float*)d_out;

    static int attr_set = 0;  // idempotent attribute set (not an allocation)
    if (!attr_set) {
        cudaFuncSetAttribute(emd_lsa_kernel,
                             cudaFuncAttributeMaxDynamicSharedMemorySize,
                             CMAT_BYTES);
        attr_set = 1;
    }

    // 3 pads keep emd_lsa_kernel at the ncu capture position (see R13).
    emd_pad_kernel<<<1, 32>>>();
    emd_pad_kernel<<<1, 32>>>();
    emd_pad_kernel<<<1, 32>>>();
    emd_lsa_kernel<<<NBATCH, NT, CMAT_BYTES>>>(pred, label);
    emd_reduce_kernel<<<1, 1>>>(out);
}